// round 8
// baseline (speedup 1.0000x reference)
#include <cuda_runtime.h>
#include <cstdint>
#include <mma.h>

using namespace nvcuda;

#define BB 8192
#define DD 1024
#define EE 8
#define HH 4096
#define RROWS (BB * 2)
#define RPAD  17408              // 16384 + 8*128 pad
#define MTILES 136               // RPAD / 128

#define BM 128
#define BN 256
#define BK 32
#define ASTR 36                  // A stride: 32 + 4 pad
#define BSTR 264                 // B stride: 256 + 8 pad
#define ASZ (BM * ASTR)          // 4608 floats
#define BSZ (BK * BSTR)          // 8448 floats
#define STG (ASZ + BSZ)          // 13056 floats / stage
#define SMEMSZ (2 * STG * 4)     // 104448 bytes

// ---------------- device scratch ----------------
__device__ int   g_tok_e[RROWS];
__device__ float g_tok_w[RROWS];
__device__ int   g_tok_pos[RROWS];
__device__ int   g_counts[EE];
__device__ int   g_poff[EE + 1];
__device__ int   g_row_token[RPAD];
__device__ int   g_tile_expert[MTILES];
__device__ float g_zr[(size_t)BB * DD];        // z rounded to tf32
__device__ float g_w2r[(size_t)EE * HH * DD];  // W2 rounded to tf32
__device__ float g_h[(size_t)RPAD * HH];       // tf32-rounded activations
__device__ float g_y[(size_t)RPAD * DD];

typedef wmma::fragment<wmma::matrix_a, 16, 16, 8, wmma::precision::tf32, wmma::row_major> FragA;
typedef wmma::fragment<wmma::matrix_b, 16, 16, 8, wmma::precision::tf32, wmma::row_major> FragB;
typedef wmma::fragment<wmma::accumulator, 16, 16, 8, float> FragC;

__device__ __forceinline__ float rtf32(float v) {
    float o;
    asm("cvt.rna.tf32.f32 %0, %1;" : "=f"(o) : "f"(v));
    return o;
}
__device__ __forceinline__ uint32_t smem_u32(const void* p) {
    uint32_t a;
    asm("{ .reg .u64 t; cvta.to.shared.u64 t, %1; cvt.u32.u64 %0, t; }" : "=r"(a) : "l"(p));
    return a;
}
__device__ __forceinline__ void cpa16(uint32_t dst, const void* src, uint32_t sz) {
    asm volatile("cp.async.cg.shared.global [%0], [%1], 16, %2;" :: "r"(dst), "l"(src), "r"(sz));
}
#define CPA_COMMIT() asm volatile("cp.async.commit_group;")
#define CPA_WAIT1()  asm volatile("cp.async.wait_group 1;")
#define CPA_WAIT0()  asm volatile("cp.async.wait_group 0;")

// ---------------------------------------------------------------------------
// init: round z -> g_zr, reset routing scratch
__global__ void init_kernel(const float* __restrict__ z) {
    int idx = blockIdx.x * blockDim.x + threadIdx.x;   // BB*DD threads
    g_zr[idx] = rtf32(z[idx]);
    if (idx < RPAD) g_row_token[idx] = -1;
    if (idx < EE)   g_counts[idx] = 0;
}

// round W2 -> g_w2r (float4 per thread)
__global__ void roundw_kernel(const float* __restrict__ src) {
    size_t i = (size_t)(blockIdx.x * blockDim.x + threadIdx.x) * 4;
    float4 v = *(const float4*)(src + i);
    v.x = rtf32(v.x); v.y = rtf32(v.y); v.z = rtf32(v.z); v.w = rtf32(v.w);
    *(float4*)(g_w2r + i) = v;
}

// ---------------------------------------------------------------------------
__global__ __launch_bounds__(256) void gate_kernel(const float* __restrict__ z,
                                                   const float* __restrict__ Wg,
                                                   const float* __restrict__ bg) {
    __shared__ float sWgT[EE * DD];
    int tid = threadIdx.x;
    for (int i = tid; i < DD * EE; i += 256) {
        int d = i >> 3, e = i & 7;
        sWgT[e * DD + d] = Wg[i];
    }
    __syncthreads();
    int warp = tid >> 5, lane = tid & 31;
    int t = blockIdx.x * 8 + warp;
    const float* zrow = z + (size_t)t * DD;
    float acc[EE];
#pragma unroll
    for (int e = 0; e < EE; e++) acc[e] = 0.0f;
    for (int d = lane; d < DD; d += 32) {
        float zv = zrow[d];
#pragma unroll
        for (int e = 0; e < EE; e++) acc[e] += zv * sWgT[e * DD + d];
    }
#pragma unroll
    for (int e = 0; e < EE; e++)
#pragma unroll
        for (int off = 16; off; off >>= 1)
            acc[e] += __shfl_xor_sync(0xffffffffu, acc[e], off);
    if (lane == 0) {
        float l[EE], m = -1e30f;
#pragma unroll
        for (int e = 0; e < EE; e++) { l[e] = acc[e] + bg[e]; m = fmaxf(m, l[e]); }
        float p[EE], Z = 0.0f;
#pragma unroll
        for (int e = 0; e < EE; e++) { p[e] = expf(l[e] - m); Z += p[e]; }
        float b1v = -1.0f, b2v = -1.0f; int i1 = 0, i2 = 0;
#pragma unroll
        for (int e = 0; e < EE; e++) {
            if (p[e] > b1v)      { b2v = b1v; i2 = i1; b1v = p[e]; i1 = e; }
            else if (p[e] > b2v) { b2v = p[e]; i2 = e; }
        }
        float invZ = 1.0f / Z;
        g_tok_e[t * 2 + 0] = i1;  g_tok_w[t * 2 + 0] = b1v * invZ;
        g_tok_e[t * 2 + 1] = i2;  g_tok_w[t * 2 + 1] = b2v * invZ;
        atomicAdd(&g_counts[i1], 1);
        atomicAdd(&g_counts[i2], 1);
    }
}

// fused offsets + tile-expert + scatter (single block, shared cursors)
__global__ void route_kernel() {
    __shared__ int s_poff[EE + 1];
    __shared__ int s_cur[EE];
    int tid = threadIdx.x;
    if (tid == 0) {
        int acc = 0;
        for (int e = 0; e < EE; e++) {
            s_poff[e] = acc;
            acc += ((g_counts[e] + 127) >> 7) << 7;
        }
        s_poff[EE] = acc;
        for (int e = 0; e <= EE; e++) g_poff[e] = s_poff[e];
    }
    if (tid < EE) s_cur[tid] = 0;
    __syncthreads();
    if (tid < MTILES) {
        int r = tid << 7;
        int ex = 0;
        for (int e = 0; e < EE; e++)
            if (r >= s_poff[e] && r < s_poff[e + 1]) ex = e;
        g_tile_expert[tid] = ex;
    }
    for (int idx = tid; idx < RROWS; idx += 256) {
        int e = g_tok_e[idx];
        int pos = s_poff[e] + atomicAdd(&s_cur[e], 1);
        g_row_token[pos] = idx >> 1;
        g_tok_pos[idx] = pos;
    }
}

// ---------------------------------------------------------------------------
// Grouped GEMM, R7-proven skeleton. Operands pre-rounded to tf32 in memory:
// WHICH=1: A = g_zr (no cvt), B = W1 raw (in-frag cvt kept); h stored rtf32.
// WHICH=2: A = g_h (no cvt), B = g_w2r (no cvt) -> fully cvt-free mainloop.
// ---------------------------------------------------------------------------
template <int WHICH>
__global__ __launch_bounds__(256) void moe_gemm(const float* __restrict__ W_glb,
                                                const float* __restrict__ bias) {
    extern __shared__ __align__(16) float smem[];
    __shared__ int stok[BM];

    const int KDIM = (WHICH == 1) ? DD : HH;
    const int NOUT = (WHICH == 1) ? HH : DD;
    const int NK = KDIM / BK;
    const int bx = blockIdx.x;
    const int n0 = blockIdx.y * BN;
    const int e = g_tile_expert[bx];
    const int row0 = bx * BM;
    const int tid = threadIdx.x, warp = tid >> 5;
    const int wm = warp >> 2, wn = warp & 3;      // 2 x 4 warps, 64 x 64 each

    const float* Wr = ((WHICH == 1) ? W_glb : (const float*)g_w2r)
                      + (size_t)e * KDIM * NOUT;

    if (tid < BM) stok[tid] = (WHICH == 1) ? g_row_token[row0 + tid] : 0;
    __syncthreads();

    const uint32_t sbase = smem_u32(smem);

    auto fill = [&](int kf, int s) {
        uint32_t sa = sbase + s * STG * 4;
        uint32_t sb = sa + ASZ * 4;
        int k0 = kf * BK;
#pragma unroll
        for (int rep = 0; rep < 12; rep++) {
            int i = rep * 256 + tid;
            if (i < 1024) {
                int row = i >> 3, q = i & 7;
                uint32_t dst = sa + (row * ASTR + q * 4) * 4;
                if (WHICH == 1) {
                    int tok = stok[row];
                    const float* src = (tok < 0) ? (const float*)g_zr
                        : g_zr + (size_t)tok * DD + k0 + q * 4;
                    cpa16(dst, src, tok < 0 ? 0u : 16u);
                } else {
                    cpa16(dst, g_h + (size_t)(row0 + row) * HH + k0 + q * 4, 16u);
                }
            } else {
                int j = i - 1024;
                int r = j >> 6, c = j & 63;
                uint32_t dst = sb + (r * BSTR + c * 4) * 4;
                cpa16(dst, Wr + (size_t)(k0 + r) * NOUT + n0 + c * 4, 16u);
            }
        }
    };

    FragC acc[4][4];
#pragma unroll
    for (int i = 0; i < 4; i++)
#pragma unroll
        for (int j = 0; j < 4; j++) wmma::fill_fragment(acc[i][j], 0.0f);

    fill(0, 0);
    CPA_COMMIT();                                 // G0

    for (int kt = 0; kt < NK; kt++) {
        if (kt + 1 < NK) fill(kt + 1, (kt + 1) & 1);
        CPA_COMMIT();                             // G_{kt+1}
        CPA_WAIT1();                              // G0..G_kt complete
        __syncthreads();
        const float* sA = smem + (kt & 1) * STG;
        const float* sB = sA + ASZ;
#pragma unroll
        for (int ks = 0; ks < BK / 8; ks++) {
            FragA a[4]; FragB b[4];
#pragma unroll
            for (int i = 0; i < 4; i++)
                wmma::load_matrix_sync(a[i], sA + (wm * 64 + i * 16) * ASTR + ks * 8, ASTR);
#pragma unroll
            for (int j = 0; j < 4; j++) {
                wmma::load_matrix_sync(b[j], sB + (ks * 8) * BSTR + wn * 64 + j * 16, BSTR);
                if (WHICH == 1) {
#pragma unroll
                    for (int t = 0; t < b[j].num_elements; t++)
                        b[j].x[t] = wmma::__float_to_tf32(b[j].x[t]);
                }
            }
#pragma unroll
            for (int i = 0; i < 4; i++)
#pragma unroll
                for (int j = 0; j < 4; j++)
                    wmma::mma_sync(acc[i][j], a[i], b[j], acc[i][j]);
        }
        __syncthreads();
    }

    // ---- epilogue ----
    CPA_WAIT0();
    __syncthreads();
    for (int i = tid; i < 16 * BN; i += 256) {
        int r = i >> 8, c = i & 255;
        smem[r * BSTR + c] = bias[(size_t)e * NOUT + n0 + c];
    }
    __syncthreads();

    FragC biasf[4];
#pragma unroll
    for (int j = 0; j < 4; j++)
        wmma::load_matrix_sync(biasf[j], smem + wn * 64 + j * 16, BSTR, wmma::mem_row_major);

    float* gdst = (WHICH == 1) ? g_h : g_y;
#pragma unroll
    for (int i = 0; i < 4; i++)
#pragma unroll
        for (int j = 0; j < 4; j++) {
#pragma unroll
            for (int t = 0; t < acc[i][j].num_elements; t++) {
                float v = acc[i][j].x[t] + biasf[j].x[t];
                if (WHICH == 1) v = rtf32(fmaxf(v, 0.0f));
                acc[i][j].x[t] = v;
            }
            wmma::store_matrix_sync(
                gdst + (size_t)(row0 + wm * 64 + i * 16) * NOUT + n0 + wn * 64 + j * 16,
                acc[i][j], NOUT, wmma::mem_row_major);
        }
}

// out[t] = w0 * y[p0] + w1 * y[p1]
__global__ void combine_kernel(float* __restrict__ out) {
    int idx = blockIdx.x * blockDim.x + threadIdx.x;   // BB*256 float4 units
    int t = idx >> 8, j = idx & 255;
    int p0 = g_tok_pos[2 * t], p1 = g_tok_pos[2 * t + 1];
    float w0 = g_tok_w[2 * t], w1 = g_tok_w[2 * t + 1];
    float4 a = ((const float4*)(g_y + (size_t)p0 * DD))[j];
    float4 b = ((const float4*)(g_y + (size_t)p1 * DD))[j];
    float4 o;
    o.x = w0 * a.x + w1 * b.x;
    o.y = w0 * a.y + w1 * b.y;
    o.z = w0 * a.z + w1 * b.z;
    o.w = w0 * a.w + w1 * b.w;
    ((float4*)out)[idx] = o;
}

// ---------------------------------------------------------------------------
extern "C" void kernel_launch(void* const* d_in, const int* in_sizes, int n_in,
                              void* d_out, int out_size) {
    const float* z  = (const float*)d_in[0];
    const float* Wg = (const float*)d_in[1];
    const float* bg = (const float*)d_in[2];
    const float* W1 = (const float*)d_in[3];
    const float* b1 = (const float*)d_in[4];
    const float* W2 = (const float*)d_in[5];
    const float* b2 = (const float*)d_in[6];
    float* out = (float*)d_out;

    cudaFuncSetAttribute(moe_gemm<1>, cudaFuncAttributeMaxDynamicSharedMemorySize, SMEMSZ);
    cudaFuncSetAttribute(moe_gemm<2>, cudaFuncAttributeMaxDynamicSharedMemorySize, SMEMSZ);

    init_kernel<<<BB * DD / 256, 256>>>(z);                          // #0
    gate_kernel<<<BB / 8, 256>>>(z, Wg, bg);                         // #1
    route_kernel<<<1, 256>>>();                                      // #2
    moe_gemm<1><<<dim3(MTILES, HH / BN), 256, SMEMSZ>>>(W1, b1);     // #3 <- ncu
    roundw_kernel<<<(EE * HH * DD / 4) / 256, 256>>>(W2);            // #4
    moe_gemm<2><<<dim3(MTILES, DD / BN), 256, SMEMSZ>>>(nullptr, b2);// #5
    combine_kernel<<<BB, 256>>>(out);                                // #6
}